// round 3
// baseline (speedup 1.0000x reference)
#include <cuda_runtime.h>
#include <cuda_bf16.h>

// WormnetCell: liquid time-constant cell, semi-implicit ODE, 6 unfolds.
// BATCH=8192 rows, U=128 units, IN=32 sensory inputs.
//
// Strategy:
//  - sigmoid(z) = 0.5 + 0.5*tanh(z/2)  -> single MUFU.TANH per synapse
//  - constant halves (0.5*W, 0.5*W*erev) folded into per-column sums (prep pass)
//  - per-synapse params packed as float4 {a, b, hWe, hW}: 1 LDG.128 per synapse
//  - one CTA (128 threads = unit index j) processes R=8 batch rows; v kept
//    transposed in smem so the row loop is broadcast LDS.128

#define UDIM 128
#define INDIM 32
#define RPB 8
#define NUNFOLDS 6

// Packed per-synapse params: {a = 0.5*sigma, b = 0.5*sigma*mu, hWe = 0.5*W*erev, hW = 0.5*W}
__device__ float4 g_Prec[UDIM * UDIM];
__device__ float4 g_Psen[INDIM * UDIM];
// Per-unit constant halves: sum over i of hWe / hW (recurrent + sensory combined)
__device__ float g_Cnum[UDIM];
__device__ float g_Cden[UDIM];

__device__ __forceinline__ float tanh_fast(float x) {
    float y;
    asm("tanh.approx.f32 %0, %1;" : "=f"(y) : "f"(x));
    return y;
}

__global__ void prep_kernel(const float* __restrict__ mu, const float* __restrict__ sig,
                            const float* __restrict__ W, const float* __restrict__ erev,
                            const float* __restrict__ smu, const float* __restrict__ ssig,
                            const float* __restrict__ sW, const float* __restrict__ serev)
{
    int idx = blockIdx.x * blockDim.x + threadIdx.x;
    if (idx < UDIM * UDIM) {
        float a = 0.5f * sig[idx];
        float w = 0.5f * W[idx];
        g_Prec[idx] = make_float4(a, a * mu[idx], w * erev[idx], w);
    }
    if (idx < INDIM * UDIM) {
        float a = 0.5f * ssig[idx];
        float w = 0.5f * sW[idx];
        g_Psen[idx] = make_float4(a, a * smu[idx], w * serev[idx], w);
    }
}

__global__ void colsum_kernel()
{
    int j = threadIdx.x;
    float cn = 0.f, cd = 0.f;
    for (int i = 0; i < UDIM; i++) {
        float4 p = g_Prec[i * UDIM + j];
        cn += p.z; cd += p.w;
    }
    for (int i = 0; i < INDIM; i++) {
        float4 p = g_Psen[i * UDIM + j];
        cn += p.z; cd += p.w;
    }
    g_Cnum[j] = cn;
    g_Cden[j] = cd;
}

__global__ void __launch_bounds__(UDIM)
worm_kernel(const float* __restrict__ inputs, const float* __restrict__ state,
            const float* __restrict__ vleak, const float* __restrict__ gleak,
            const float* __restrict__ cm,
            const float* __restrict__ in_w, const float* __restrict__ in_b,
            const float* __restrict__ out_w, const float* __restrict__ out_b,
            float* __restrict__ out_y, float* __restrict__ out_v)
{
    __shared__ float vT[UDIM * RPB];   // vT[i*RPB + r] : unit i of row r
    __shared__ float xT[INDIM * RPB];  // xT[i*RPB + r]

    const int j = threadIdx.x;                        // unit index 0..127
    const long long row0 = (long long)blockIdx.x * RPB;

    // Load state (transposed into smem): coalesced gmem reads
    #pragma unroll
    for (int r = 0; r < RPB; r++)
        vT[j * RPB + r] = state[(row0 + r) * UDIM + j];

    // Load inputs with affine map: 2 strided passes of 128 threads over 32*8 values
    #pragma unroll
    for (int k = 0; k < (INDIM * RPB) / UDIM; k++) {
        int idx = k * UDIM + j;
        int r = idx / INDIM, i = idx % INDIM;
        xT[i * RPB + r] = fmaf(inputs[(row0 + r) * INDIM + i], in_w[i], in_b[i]);
    }
    __syncthreads();

    // Base accumulators = constant halves + sensory contribution (fixed across unfolds)
    float bnum[RPB], bden[RPB];
    {
        float c0 = g_Cnum[j], d0 = g_Cden[j];
        #pragma unroll
        for (int r = 0; r < RPB; r++) { bnum[r] = c0; bden[r] = d0; }
    }

    #pragma unroll 4
    for (int i = 0; i < INDIM; i++) {
        float4 p = g_Psen[i * UDIM + j];
        const float4* xp = reinterpret_cast<const float4*>(&xT[i * RPB]);
        float4 x0 = xp[0], x1 = xp[1];
        float xv[RPB] = {x0.x, x0.y, x0.z, x0.w, x1.x, x1.y, x1.z, x1.w};
        #pragma unroll
        for (int r = 0; r < RPB; r++) {
            float th = tanh_fast(fmaf(p.x, xv[r], -p.y));
            bnum[r] = fmaf(p.z, th, bnum[r]);
            bden[r] = fmaf(p.w, th, bden[r]);
        }
    }

    const float cmj = cm[j];
    const float glj = gleak[j];
    const float gvj = glj * vleak[j];
    const float cgj = cmj + glj;

    float vcur[RPB];
    #pragma unroll
    for (int r = 0; r < RPB; r++) vcur[r] = vT[j * RPB + r];

    for (int t = 0; t < NUNFOLDS; t++) {
        float num[RPB], den[RPB];
        #pragma unroll
        for (int r = 0; r < RPB; r++) { num[r] = bnum[r]; den[r] = bden[r]; }

        #pragma unroll 2
        for (int i = 0; i < UDIM; i++) {
            float4 p = g_Prec[i * UDIM + j];                       // 1x LDG.128, L2-hot
            const float4* vp = reinterpret_cast<const float4*>(&vT[i * RPB]);
            float4 v0 = vp[0], v1 = vp[1];                        // broadcast LDS.128
            float vv[RPB] = {v0.x, v0.y, v0.z, v0.w, v1.x, v1.y, v1.z, v1.w};
            #pragma unroll
            for (int r = 0; r < RPB; r++) {
                float th = tanh_fast(fmaf(p.x, vv[r], -p.y));
                num[r] = fmaf(p.z, th, num[r]);
                den[r] = fmaf(p.w, th, den[r]);
            }
        }

        __syncthreads();  // all reads of vT done before overwrite
        #pragma unroll
        for (int r = 0; r < RPB; r++) {
            float vn = __fdividef(fmaf(cmj, vcur[r], gvj + num[r]), cgj + den[r]);
            vcur[r] = vn;
            vT[j * RPB + r] = vn;
        }
        __syncthreads();
    }

    // Outputs: full final state v, plus first unit through output affine map
    if (out_v) {
        #pragma unroll
        for (int r = 0; r < RPB; r++)
            out_v[(row0 + r) * UDIM + j] = vcur[r];
    }
    if (out_y && j == 0) {
        float ow = out_w[0], ob = out_b[0];
        #pragma unroll
        for (int r = 0; r < RPB; r++)
            out_y[row0 + r] = fmaf(vcur[r], ow, ob);
    }
}

extern "C" void kernel_launch(void* const* d_in, const int* in_sizes, int n_in,
                              void* d_out, int out_size)
{
    const float* inputs = (const float*)d_in[0];
    const float* state  = (const float*)d_in[1];
    const float* smu    = (const float*)d_in[2];
    const float* ssig   = (const float*)d_in[3];
    const float* sW     = (const float*)d_in[4];
    const float* serev  = (const float*)d_in[5];
    const float* mu     = (const float*)d_in[6];
    const float* sig    = (const float*)d_in[7];
    const float* W      = (const float*)d_in[8];
    const float* erev   = (const float*)d_in[9];
    const float* vleak  = (const float*)d_in[10];
    const float* gleak  = (const float*)d_in[11];
    const float* cm     = (const float*)d_in[12];
    const float* in_w   = (const float*)d_in[13];
    const float* in_b   = (const float*)d_in[14];
    const float* out_w  = (const float*)d_in[15];
    const float* out_b  = (const float*)d_in[16];

    const int batch = in_sizes[1] / UDIM;   // 8192

    float* out   = (float*)d_out;
    float* out_y = nullptr;
    float* out_v = nullptr;
    if (out_size == batch + batch * UDIM) {       // (outputs, v) concatenated
        out_y = out;
        out_v = out + batch;
    } else if (out_size == batch * UDIM) {        // v only
        out_v = out;
    } else {                                      // outputs only
        out_y = out;
    }

    prep_kernel<<<(UDIM * UDIM + 255) / 256, 256>>>(mu, sig, W, erev, smu, ssig, sW, serev);
    colsum_kernel<<<1, UDIM>>>();
    worm_kernel<<<batch / RPB, UDIM>>>(inputs, state, vleak, gleak, cm,
                                       in_w, in_b, out_w, out_b, out_y, out_v);
}

// round 5
// speedup vs baseline: 1.0274x; 1.0274x over previous
#include <cuda_runtime.h>
#include <cuda_bf16.h>

// WormnetCell: liquid time-constant cell, semi-implicit ODE, 6 unfolds.
// BATCH=8192 rows, U=128 units, IN=32 sensory inputs.
//
// R3 changes vs R2 (229.5us):
//  - recurrent i-loop unrolled x4 with rotating 4-deep float4 param prefetch
//    (covers L2 latency ~250cyc at ~64cyc/group/warp cadence)
//  - __ldg on all param streams
//  - __launch_bounds__(128,4): keep 4 CTAs/SM under added prefetch registers
//  - prep + colsum merged into one kernel (2 launches per call)

#define UDIM 128
#define INDIM 32
#define RPB 8
#define NUNFOLDS 6

// Packed per-synapse params: {a = 0.5*sigma, b = 0.5*sigma*mu, hWe = 0.5*W*erev, hW = 0.5*W}
__device__ float4 g_Prec[UDIM * UDIM];
__device__ float4 g_Psen[INDIM * UDIM];
// Per-unit constant halves: sum over i of hWe / hW (recurrent + sensory combined)
__device__ float g_Cnum[UDIM];
__device__ float g_Cden[UDIM];

__device__ __forceinline__ float tanh_fast(float x) {
    float y;
    asm("tanh.approx.f32 %0, %1;" : "=f"(y) : "f"(x));
    return y;
}

// One block per unit-column j (128 blocks x 160 threads).
// Thread i packs synapse (i, j) params and participates in the column reduction.
__global__ void prep_kernel(const float* __restrict__ mu, const float* __restrict__ sig,
                            const float* __restrict__ W, const float* __restrict__ erev,
                            const float* __restrict__ smu, const float* __restrict__ ssig,
                            const float* __restrict__ sW, const float* __restrict__ serev)
{
    __shared__ float sn[UDIM + INDIM];
    __shared__ float sd[UDIM + INDIM];
    const int j = blockIdx.x;
    const int i = threadIdx.x;

    float4 p;
    if (i < UDIM) {
        int idx = i * UDIM + j;
        float a = 0.5f * sig[idx];
        float w = 0.5f * W[idx];
        p = make_float4(a, a * mu[idx], w * erev[idx], w);
        g_Prec[idx] = p;
    } else {
        int idx = (i - UDIM) * UDIM + j;
        float a = 0.5f * ssig[idx];
        float w = 0.5f * sW[idx];
        p = make_float4(a, a * smu[idx], w * serev[idx], w);
        g_Psen[idx] = p;
    }
    sn[i] = p.z;
    sd[i] = p.w;
    __syncthreads();

    if (i == 0) {
        float cn = 0.f, cd = 0.f;
        #pragma unroll 8
        for (int k = 0; k < UDIM + INDIM; k++) { cn += sn[k]; cd += sd[k]; }
        g_Cnum[j] = cn;
        g_Cden[j] = cd;
    }
}

__global__ void __launch_bounds__(UDIM, 4)
worm_kernel(const float* __restrict__ inputs, const float* __restrict__ state,
            const float* __restrict__ vleak, const float* __restrict__ gleak,
            const float* __restrict__ cm,
            const float* __restrict__ in_w, const float* __restrict__ in_b,
            const float* __restrict__ out_w, const float* __restrict__ out_b,
            float* __restrict__ out_y, float* __restrict__ out_v)
{
    __shared__ __align__(16) float vT[UDIM * RPB];   // vT[i*RPB + r]
    __shared__ __align__(16) float xT[INDIM * RPB];  // xT[i*RPB + r]

    const int j = threadIdx.x;                        // unit index 0..127
    const long long row0 = (long long)blockIdx.x * RPB;

    // State -> smem transposed (coalesced gmem reads)
    #pragma unroll
    for (int r = 0; r < RPB; r++)
        vT[j * RPB + r] = state[(row0 + r) * UDIM + j];

    // Inputs with affine map
    #pragma unroll
    for (int k = 0; k < (INDIM * RPB) / UDIM; k++) {
        int idx = k * UDIM + j;
        int r = idx / INDIM, i = idx % INDIM;
        xT[i * RPB + r] = fmaf(inputs[(row0 + r) * INDIM + i], __ldg(&in_w[i]), __ldg(&in_b[i]));
    }
    __syncthreads();

    // Base accumulators = constant halves + sensory contribution (fixed across unfolds)
    float bnum[RPB], bden[RPB];
    {
        float c0 = g_Cnum[j], d0 = g_Cden[j];
        #pragma unroll
        for (int r = 0; r < RPB; r++) { bnum[r] = c0; bden[r] = d0; }
    }

    #pragma unroll 4
    for (int i = 0; i < INDIM; i++) {
        float4 p = __ldg(&g_Psen[i * UDIM + j]);
        const float4* xp = reinterpret_cast<const float4*>(&xT[i * RPB]);
        float4 x0 = xp[0], x1 = xp[1];
        float xv[RPB] = {x0.x, x0.y, x0.z, x0.w, x1.x, x1.y, x1.z, x1.w};
        #pragma unroll
        for (int r = 0; r < RPB; r++) {
            float th = tanh_fast(fmaf(p.x, xv[r], -p.y));
            bnum[r] = fmaf(p.z, th, bnum[r]);
            bden[r] = fmaf(p.w, th, bden[r]);
        }
    }

    const float cmj = cm[j];
    const float glj = gleak[j];
    const float gvj = glj * vleak[j];
    const float cgj = cmj + glj;

    float vcur[RPB];
    #pragma unroll
    for (int r = 0; r < RPB; r++) vcur[r] = vT[j * RPB + r];

    for (int t = 0; t < NUNFOLDS; t++) {
        float num[RPB], den[RPB];
        #pragma unroll
        for (int r = 0; r < RPB; r++) { num[r] = bnum[r]; den[r] = bden[r]; }

        // 4-deep rotating prefetch of the param stream (hides L2 latency).
        float4 P[4], Q[4];
        #pragma unroll
        for (int k = 0; k < 4; k++)
            P[k] = __ldg(&g_Prec[k * UDIM + j]);

        #pragma unroll 1
        for (int i = 0; i < UDIM; i += 4) {
            const int nx = (i + 4 < UDIM) ? (i + 4) : 0;   // wrap: harmless dummy load
            #pragma unroll
            for (int k = 0; k < 4; k++)
                Q[k] = __ldg(&g_Prec[(nx + k) * UDIM + j]);

            #pragma unroll
            for (int k = 0; k < 4; k++) {
                const float4 p = P[k];
                const float4* vp = reinterpret_cast<const float4*>(&vT[(i + k) * RPB]);
                float4 v0 = vp[0], v1 = vp[1];               // broadcast LDS.128
                float vv[RPB] = {v0.x, v0.y, v0.z, v0.w, v1.x, v1.y, v1.z, v1.w};
                #pragma unroll
                for (int r = 0; r < RPB; r++) {
                    float th = tanh_fast(fmaf(p.x, vv[r], -p.y));
                    num[r] = fmaf(p.z, th, num[r]);
                    den[r] = fmaf(p.w, th, den[r]);
                }
            }

            #pragma unroll
            for (int k = 0; k < 4; k++) P[k] = Q[k];
        }

        __syncthreads();  // all reads of vT done before overwrite
        #pragma unroll
        for (int r = 0; r < RPB; r++) {
            float vn = __fdividef(fmaf(cmj, vcur[r], gvj + num[r]), cgj + den[r]);
            vcur[r] = vn;
            vT[j * RPB + r] = vn;
        }
        __syncthreads();
    }

    // Outputs: full final state v, plus first unit through output affine map
    if (out_v) {
        #pragma unroll
        for (int r = 0; r < RPB; r++)
            out_v[(row0 + r) * UDIM + j] = vcur[r];
    }
    if (out_y && j == 0) {
        float ow = __ldg(&out_w[0]), ob = __ldg(&out_b[0]);
        #pragma unroll
        for (int r = 0; r < RPB; r++)
            out_y[row0 + r] = fmaf(vcur[r], ow, ob);
    }
}

extern "C" void kernel_launch(void* const* d_in, const int* in_sizes, int n_in,
                              void* d_out, int out_size)
{
    const float* inputs = (const float*)d_in[0];
    const float* state  = (const float*)d_in[1];
    const float* smu    = (const float*)d_in[2];
    const float* ssig   = (const float*)d_in[3];
    const float* sW     = (const float*)d_in[4];
    const float* serev  = (const float*)d_in[5];
    const float* mu     = (const float*)d_in[6];
    const float* sig    = (const float*)d_in[7];
    const float* W      = (const float*)d_in[8];
    const float* erev   = (const float*)d_in[9];
    const float* vleak  = (const float*)d_in[10];
    const float* gleak  = (const float*)d_in[11];
    const float* cm     = (const float*)d_in[12];
    const float* in_w   = (const float*)d_in[13];
    const float* in_b   = (const float*)d_in[14];
    const float* out_w  = (const float*)d_in[15];
    const float* out_b  = (const float*)d_in[16];

    const int batch = in_sizes[1] / UDIM;   // 8192

    float* out   = (float*)d_out;
    float* out_y = nullptr;
    float* out_v = nullptr;
    if (out_size == batch + batch * UDIM) {       // (outputs, v) concatenated
        out_y = out;
        out_v = out + batch;
    } else if (out_size == batch * UDIM) {        // v only
        out_v = out;
    } else {                                      // outputs only
        out_y = out;
    }

    prep_kernel<<<UDIM, UDIM + INDIM>>>(mu, sig, W, erev, smu, ssig, sW, serev);
    worm_kernel<<<batch / RPB, UDIM>>>(inputs, state, vleak, gleak, cm,
                                       in_w, in_b, out_w, out_b, out_y, out_v);
}

// round 7
// speedup vs baseline: 1.0342x; 1.0066x over previous
#include <cuda_runtime.h>
#include <cuda_fp16.h>

// WormnetCell: liquid time-constant cell, semi-implicit ODE, 6 unfolds.
// BATCH=8192 rows, U=128 units, IN=32 sensory inputs.
//
// R6 (= R5 resubmit after infra failure, + fp32 vcur registers for the update):
//  - tanh.approx.f16x2: 2 sigmoids per MUFU op (halves the XU floor)
//  - v mirrored in smem as half2 row-pairs (8 rows -> uint4, one LDS.128/i)
//  - args + partial accumulation in half2 (HFMA2), flushed to fp32 via
//    add.rn.f32x2 every 4 i-steps (amortizes conversions 4x)
//  - recurrent params pre-packed half2-broadcast, 16B -> 1 LDG.128/i
//  - __launch_bounds__(128,7): 1036 concurrent CTAs >= 1024 grid -> 1 wave
//  - v update term cm*v uses fp32 registers (no half quant in the dominant term)

#define UDIM 128
#define INDIM 32
#define RPB 8
#define NUNFOLDS 6

typedef unsigned long long u64;

// Recurrent params, half2-broadcast: {a2, nb2, we2, w2} with a=sigma/2, nb=-sigma*mu/2,
// we=0.5*W*erev, w=0.5*W (each duplicated into both halves).
__device__ uint4  g_PrecH[UDIM * UDIM];
// Sensory params fp32: {a, b, we, w}
__device__ float4 g_Psen[INDIM * UDIM];
// Per-unit constant halves (sum of we / w over all 160 inputs), fp32
__device__ float  g_Cnum[UDIM];
__device__ float  g_Cden[UDIM];

__device__ __forceinline__ float tanh_fast(float x) {
    float y; asm("tanh.approx.f32 %0, %1;" : "=f"(y) : "f"(x)); return y;
}
__device__ __forceinline__ unsigned tanh2u(unsigned x) {
    unsigned y; asm("tanh.approx.f16x2 %0, %1;" : "=r"(y) : "r"(x)); return y;
}
__device__ __forceinline__ u64 add_f32x2(u64 a, u64 b) {
    u64 d; asm("add.rn.f32x2 %0, %1, %2;" : "=l"(d) : "l"(a), "l"(b)); return d;
}
__device__ __forceinline__ u64 pack2(float lo, float hi) {
    u64 r; asm("mov.b64 %0, {%1, %2};" : "=l"(r) : "f"(lo), "f"(hi)); return r;
}
__device__ __forceinline__ float2 unpack2(u64 v) {
    float2 f; asm("mov.b64 {%0, %1}, %2;" : "=f"(f.x), "=f"(f.y) : "l"(v)); return f;
}
__device__ __forceinline__ __half2 h2bits(unsigned u) {
    __half2 h; *reinterpret_cast<unsigned*>(&h) = u; return h;
}
__device__ __forceinline__ unsigned bitsh2(__half2 h) {
    return *reinterpret_cast<unsigned*>(&h);
}

// One block per unit-column j (128 blocks x 160 threads).
__global__ void prep_kernel(const float* __restrict__ mu, const float* __restrict__ sig,
                            const float* __restrict__ W, const float* __restrict__ erev,
                            const float* __restrict__ smu, const float* __restrict__ ssig,
                            const float* __restrict__ sW, const float* __restrict__ serev)
{
    __shared__ float sn[UDIM + INDIM];
    __shared__ float sd[UDIM + INDIM];
    const int j = blockIdx.x;
    const int i = threadIdx.x;

    float we, w;
    if (i < UDIM) {
        int idx = i * UDIM + j;
        float a = 0.5f * sig[idx];
        float b = a * mu[idx];
        w  = 0.5f * W[idx];
        we = w * erev[idx];
        g_PrecH[idx] = make_uint4(bitsh2(__floats2half2_rn(a,  a)),
                                  bitsh2(__floats2half2_rn(-b, -b)),
                                  bitsh2(__floats2half2_rn(we, we)),
                                  bitsh2(__floats2half2_rn(w,  w)));
    } else {
        int idx = (i - UDIM) * UDIM + j;
        float a = 0.5f * ssig[idx];
        w  = 0.5f * sW[idx];
        we = w * serev[idx];
        g_Psen[idx] = make_float4(a, a * smu[idx], we, w);
    }
    sn[i] = we;
    sd[i] = w;
    __syncthreads();

    if (i == 0) {
        float cn = 0.f, cd = 0.f;
        #pragma unroll 8
        for (int k = 0; k < UDIM + INDIM; k++) { cn += sn[k]; cd += sd[k]; }
        g_Cnum[j] = cn;
        g_Cden[j] = cd;
    }
}

__global__ void __launch_bounds__(UDIM, 7)
worm_kernel(const float* __restrict__ inputs, const float* __restrict__ state,
            const float* __restrict__ vleak, const float* __restrict__ gleak,
            const float* __restrict__ cm,
            const float* __restrict__ in_w, const float* __restrict__ in_b,
            const float* __restrict__ out_w, const float* __restrict__ out_b,
            float* __restrict__ out_y, float* __restrict__ out_v)
{
    __shared__ __align__(16) uint4 vHs[UDIM];          // v as 4x half2 (8 rows) per unit
    __shared__ u64  sBn[UDIM * 4];                     // base num, f32x2 per row-pair
    __shared__ u64  sBd[UDIM * 4];                     // base den
    __shared__ float xT[INDIM * RPB];

    const int j = threadIdx.x;                         // unit index 0..127
    const long long row0 = (long long)blockIdx.x * RPB;

    // ---- load state (fp32 registers) + half2 mirror in smem ----
    float vcur[RPB];
    #pragma unroll
    for (int r = 0; r < RPB; r++)
        vcur[r] = state[(row0 + r) * UDIM + j];
    vHs[j] = make_uint4(bitsh2(__floats2half2_rn(vcur[0], vcur[1])),
                        bitsh2(__floats2half2_rn(vcur[2], vcur[3])),
                        bitsh2(__floats2half2_rn(vcur[4], vcur[5])),
                        bitsh2(__floats2half2_rn(vcur[6], vcur[7])));

    // ---- inputs with affine map ----
    #pragma unroll
    for (int k = 0; k < (INDIM * RPB) / UDIM; k++) {
        int idx = k * UDIM + j;
        int r = idx / INDIM, i = idx % INDIM;
        xT[i * RPB + r] = fmaf(inputs[(row0 + r) * INDIM + i], __ldg(&in_w[i]), __ldg(&in_b[i]));
    }
    __syncthreads();

    // ---- sensory contribution (fp32, 4% of total work) + constant halves ----
    {
        float bnum[RPB], bden[RPB];
        float c0 = g_Cnum[j], d0 = g_Cden[j];
        #pragma unroll
        for (int r = 0; r < RPB; r++) { bnum[r] = c0; bden[r] = d0; }

        #pragma unroll 4
        for (int i = 0; i < INDIM; i++) {
            float4 p = __ldg(&g_Psen[i * UDIM + j]);
            const float4* xp = reinterpret_cast<const float4*>(&xT[i * RPB]);
            float4 x0 = xp[0], x1 = xp[1];
            float xv[RPB] = {x0.x, x0.y, x0.z, x0.w, x1.x, x1.y, x1.z, x1.w};
            #pragma unroll
            for (int r = 0; r < RPB; r++) {
                float th = tanh_fast(fmaf(p.x, xv[r], -p.y));
                bnum[r] = fmaf(p.z, th, bnum[r]);
                bden[r] = fmaf(p.w, th, bden[r]);
            }
        }
        #pragma unroll
        for (int p = 0; p < 4; p++) {
            sBn[j * 4 + p] = pack2(bnum[2 * p], bnum[2 * p + 1]);
            sBd[j * 4 + p] = pack2(bden[2 * p], bden[2 * p + 1]);
        }
    }

    const float cmj = cm[j];
    const float glj = gleak[j];
    const float gvj = glj * vleak[j];
    const float cgj = cmj + glj;

    float ow = 0.f, ob = 0.f;
    if (out_y && j == 0) { ow = __ldg(&out_w[0]); ob = __ldg(&out_b[0]); }

    for (int t = 0; t < NUNFOLDS; t++) {
        u64 num2[4], den2[4];
        #pragma unroll
        for (int p = 0; p < 4; p++) { num2[p] = sBn[j * 4 + p]; den2[p] = sBd[j * 4 + p]; }

        // chunk-0 params prefetched; double-buffer by chunks of 4
        uint4 nxt[4];
        #pragma unroll
        for (int c = 0; c < 4; c++) nxt[c] = __ldg(&g_PrecH[c * UDIM + j]);

        #pragma unroll 1
        for (int i0 = 0; i0 < UDIM; i0 += 4) {
            uint4 cur[4];
            #pragma unroll
            for (int c = 0; c < 4; c++) cur[c] = nxt[c];
            const int n0 = (i0 + 4) & (UDIM - 1);          // wrap: harmless re-load
            #pragma unroll
            for (int c = 0; c < 4; c++) nxt[c] = __ldg(&g_PrecH[(n0 + c) * UDIM + j]);

            __half2 pn[4], pd[4];
            #pragma unroll
            for (int c = 0; c < 4; c++) {
                const __half2 a2  = h2bits(cur[c].x);
                const __half2 nb2 = h2bits(cur[c].y);
                const __half2 we2 = h2bits(cur[c].z);
                const __half2 w2  = h2bits(cur[c].w);
                const uint4 vh = vHs[i0 + c];              // broadcast LDS.128
                const unsigned vv[4] = {vh.x, vh.y, vh.z, vh.w};
                #pragma unroll
                for (int p = 0; p < 4; p++) {
                    __half2 arg = __hfma2(a2, h2bits(vv[p]), nb2);
                    __half2 th  = h2bits(tanh2u(bitsh2(arg)));
                    if (c == 0) {
                        pn[p] = __hmul2(we2, th);
                        pd[p] = __hmul2(w2,  th);
                    } else {
                        pn[p] = __hfma2(we2, th, pn[p]);
                        pd[p] = __hfma2(w2,  th, pd[p]);
                    }
                }
            }
            // flush half2 partials (|sum|<=2, safe in fp16) into fp32 accumulators
            #pragma unroll
            for (int p = 0; p < 4; p++) {
                float2 fn = __half22float2(pn[p]);
                float2 fd = __half22float2(pd[p]);
                num2[p] = add_f32x2(num2[p], pack2(fn.x, fn.y));
                den2[p] = add_f32x2(den2[p], pack2(fd.x, fd.y));
            }
        }

        __syncthreads();   // all reads of vHs complete before overwrite

        unsigned newh[4];
        #pragma unroll
        for (int p = 0; p < 4; p++) {
            float2 nf = unpack2(num2[p]);
            float2 df = unpack2(den2[p]);
            float vn0 = __fdividef(fmaf(cmj, vcur[2 * p],     gvj + nf.x), cgj + df.x);
            float vn1 = __fdividef(fmaf(cmj, vcur[2 * p + 1], gvj + nf.y), cgj + df.y);
            vcur[2 * p]     = vn0;
            vcur[2 * p + 1] = vn1;
            newh[p] = bitsh2(__floats2half2_rn(vn0, vn1));
        }
        vHs[j] = make_uint4(newh[0], newh[1], newh[2], newh[3]);
        __syncthreads();
    }

    // ---- outputs in fp32 (never rounded through half) ----
    if (out_v) {
        #pragma unroll
        for (int r = 0; r < RPB; r++)
            out_v[(row0 + r) * UDIM + j] = vcur[r];
    }
    if (out_y && j == 0) {
        #pragma unroll
        for (int r = 0; r < RPB; r++)
            out_y[row0 + r] = fmaf(vcur[r], ow, ob);
    }
}

extern "C" void kernel_launch(void* const* d_in, const int* in_sizes, int n_in,
                              void* d_out, int out_size)
{
    const float* inputs = (const float*)d_in[0];
    const float* state  = (const float*)d_in[1];
    const float* smu    = (const float*)d_in[2];
    const float* ssig   = (const float*)d_in[3];
    const float* sW     = (const float*)d_in[4];
    const float* serev  = (const float*)d_in[5];
    const float* mu     = (const float*)d_in[6];
    const float* sig    = (const float*)d_in[7];
    const float* W      = (const float*)d_in[8];
    const float* erev   = (const float*)d_in[9];
    const float* vleak  = (const float*)d_in[10];
    const float* gleak  = (const float*)d_in[11];
    const float* cm     = (const float*)d_in[12];
    const float* in_w   = (const float*)d_in[13];
    const float* in_b   = (const float*)d_in[14];
    const float* out_w  = (const float*)d_in[15];
    const float* out_b  = (const float*)d_in[16];

    const int batch = in_sizes[1] / UDIM;   // 8192

    float* out   = (float*)d_out;
    float* out_y = nullptr;
    float* out_v = nullptr;
    if (out_size == batch + batch * UDIM) {       // (outputs, v) concatenated
        out_y = out;
        out_v = out + batch;
    } else if (out_size == batch * UDIM) {        // v only
        out_v = out;
    } else {                                      // outputs only
        out_y = out;
    }

    prep_kernel<<<UDIM, UDIM + INDIM>>>(mu, sig, W, erev, smu, ssig, sW, serev);
    worm_kernel<<<batch / RPB, UDIM>>>(inputs, state, vleak, gleak, cm,
                                       in_w, in_b, out_w, out_b, out_y, out_v);
}